// round 16
// baseline (speedup 1.0000x reference)
#include <cuda_runtime.h>
#include <cuda_fp16.h>
#include <cstdint>
#include <math.h>

#define B_   2
#define S_   1024
#define HID_ 1024
#define NH   16
#define HD   64
#define RTAB 257
#define MAXREL 128
#define INV_SCALE 0.125f   // 1/sqrt(64)
#define LOG2E 1.44269504089f

// ---------------- scratch (no allocations allowed) ----------------
__device__ __half   g_Q[B_ * S_ * HID_];
__device__ __half   g_K[B_ * S_ * HID_];
__device__ __half   g_V[B_ * S_ * HID_];
__device__ __half   g_X[B_ * S_ * HID_];
__device__ uint16_t g_pidx[B_ * S_ * S_];        // FRAGMENT-ORDER permuted indices
__device__ __half   g_A16[3][B_ * S_ * HID_];    // fp16 inputs (q,k,v)
__device__ __half   g_W16[4][HID_ * HID_];       // fp16 weights (Wq,Wk,Wv,Wo)

// ================================================================
// helpers
// ================================================================
__device__ __forceinline__ uint32_t smaddr(const void* p) {
    return (uint32_t)__cvta_generic_to_shared(p);
}
__device__ __forceinline__ uint32_t h2u(__half2 h) { return *(uint32_t*)&h; }
__device__ __forceinline__ float ex2(float x) {
    float y;
    asm("ex2.approx.f32 %0, %1;" : "=f"(y) : "f"(x));
    return y;
}

__device__ __forceinline__ void ldsm4(uint32_t* r, uint32_t a) {
    asm volatile("ldmatrix.sync.aligned.m8n8.x4.shared.b16 {%0,%1,%2,%3}, [%4];"
        : "=r"(r[0]), "=r"(r[1]), "=r"(r[2]), "=r"(r[3]) : "r"(a));
}
__device__ __forceinline__ void ldsm4t(uint32_t* r, uint32_t a) {
    asm volatile("ldmatrix.sync.aligned.m8n8.x4.trans.shared.b16 {%0,%1,%2,%3}, [%4];"
        : "=r"(r[0]), "=r"(r[1]), "=r"(r[2]), "=r"(r[3]) : "r"(a));
}
__device__ __forceinline__ void mma_f16(float* d, const uint32_t* a, const uint32_t* b) {
    asm volatile("mma.sync.aligned.m16n8k16.row.col.f32.f16.f16.f32 "
        "{%0,%1,%2,%3}, {%4,%5,%6,%7}, {%8,%9}, {%0,%1,%2,%3};"
        : "+f"(d[0]), "+f"(d[1]), "+f"(d[2]), "+f"(d[3])
        : "r"(a[0]), "r"(a[1]), "r"(a[2]), "r"(a[3]), "r"(b[0]), "r"(b[1]));
}
#define CP_ASYNC16(dst, src) \
    asm volatile("cp.async.cg.shared.global [%0], [%1], 16;" :: "r"(dst), "l"(src))
#define CP_COMMIT()  asm volatile("cp.async.commit_group;" ::: "memory")
#define CP_WAIT0()   asm volatile("cp.async.wait_group 0;" ::: "memory")
#define CP_WAIT1()   asm volatile("cp.async.wait_group 1;" ::: "memory")

// ================================================================
// pack dist+mask -> uint16 index, PERMUTED to mma fragment order
// ================================================================
__global__ __launch_bounds__(256)
void pack_kernel(const int* __restrict__ dist, const uint8_t* __restrict__ mask)
{
    const size_t idx  = (size_t)blockIdx.x * 256 + threadIdx.x;
    const size_t base = idx * 8;
    const int    k8   = (int)(base & (S_ - 1));
    const int    j    = (k8 >> 3) & 3;
    const size_t blkb = base - (size_t)(k8 & 31);

    int4   d0 = *(const int4*)(dist + base);
    int4   d1 = *(const int4*)(dist + base + 4);
    uchar4 m0 = *(const uchar4*)(mask + base);
    uchar4 m1 = *(const uchar4*)(mask + base + 4);

    uint16_t o[8];
    o[0] = m0.x ? 257 : (uint16_t)(d0.x + MAXREL);
    o[1] = m0.y ? 257 : (uint16_t)(d0.y + MAXREL);
    o[2] = m0.z ? 257 : (uint16_t)(d0.z + MAXREL);
    o[3] = m0.w ? 257 : (uint16_t)(d0.w + MAXREL);
    o[4] = m1.x ? 257 : (uint16_t)(d1.x + MAXREL);
    o[5] = m1.y ? 257 : (uint16_t)(d1.y + MAXREL);
    o[6] = m1.z ? 257 : (uint16_t)(d1.z + MAXREL);
    o[7] = m1.w ? 257 : (uint16_t)(d1.w + MAXREL);

#pragma unroll
    for (int lq = 0; lq < 4; lq++) {
        uint32_t pair = (uint32_t)o[2 * lq] | ((uint32_t)o[2 * lq + 1] << 16);
        *(uint32_t*)(g_pidx + blkb + lq * 8 + j * 2) = pair;
    }
}

// ================================================================
// fp32 -> fp16 convert, 7 segments
// ================================================================
struct CvtArgs {
    const float* src[7];
    __half*      dst[7];
    int          n[7];
};

__global__ __launch_bounds__(256)
void cvt_kernel(CvtArgs ca)
{
    const int seg = blockIdx.y;
    const int i   = blockIdx.x * 256 + threadIdx.x;
    if (i * 8 >= ca.n[seg]) return;
    const float4* sp = (const float4*)ca.src[seg] + i * 2;
    float4 a = sp[0], b2 = sp[1];
    uint4 u;
    u.x = h2u(__floats2half2_rn(a.x, a.y));
    u.y = h2u(__floats2half2_rn(a.z, a.w));
    u.z = h2u(__floats2half2_rn(b2.x, b2.y));
    u.w = h2u(__floats2half2_rn(b2.z, b2.w));
    ((uint4*)ca.dst[seg])[i] = u;
}

// ================================================================
// fp16 HMMA GEMM, cp.async double-buffered, BK=64, DYNAMIC smem (70KB).
// C[M,N] = A[M,K] @ W[K,N] + bias[N].
// ================================================================
#define BM 128
#define BN 128
#define BKC 64
#define NCHUNK (HID_ / BKC)      // 16
#define LDAH 72                   // 64 + 8 halves (144B row: conflict-free ldsm)
#define LDBH 136                  // 128 + 8 halves
#define GEMM_AS_STG (BM * LDAH)           // halves per A stage
#define GEMM_BS_STG (BKC * LDBH)          // halves per B stage
#define GEMM_SMEM ((2 * GEMM_AS_STG + 2 * GEMM_BS_STG) * 2)   // 71680 B

struct GemmBatch {
    const __half* A[3];
    const __half* W[3];
    const float*  b[3];
    void*         C[3];
};

template<int OUTH>
__global__ __launch_bounds__(256)
void gemm_mma_kernel(GemmBatch gb)
{
    extern __shared__ __half gsm[];
    __half* AsBase = gsm;                          // 2 stages
    __half* BsBase = gsm + 2 * GEMM_AS_STG;        // 2 stages

    const int z = blockIdx.z;
    const __half* A    = gb.A[z];
    const __half* W    = gb.W[z];
    const float*  bias = gb.b[z];

    const int tid  = threadIdx.x;
    const int wid  = tid >> 5;
    const int lane = tid & 31;
    const int wm   = wid & 3;
    const int wn   = wid >> 2;
    const int gq   = lane >> 2;
    const int lq   = lane & 3;

    const int brow = blockIdx.y * BM;
    const int bcol = blockIdx.x * BN;

    // loaders: A 2 thr/row x 4x16B; B 4 thr/row x 4x16B
    const int arow = tid >> 1;            // 0..127
    const int acb  = (tid & 1) * 32;      // halves
    const int bro  = tid >> 2;            // 0..63
    const int bcb  = (tid & 3) * 32;      // halves

    const __half* aptr = A + (size_t)(brow + arow) * HID_ + acb;
    const __half* wptr = W + (size_t)bro * HID_ + bcol + bcb;

    auto issue = [&](int c, int s) {
        const int k0 = c * BKC;
        const uint32_t ad = smaddr(AsBase + s * GEMM_AS_STG + arow * LDAH + acb);
        const uint32_t bd = smaddr(BsBase + s * GEMM_BS_STG + bro * LDBH + bcb);
#pragma unroll
        for (int m = 0; m < 4; m++)
            CP_ASYNC16(ad + m * 16, aptr + k0 + m * 8);
#pragma unroll
        for (int m = 0; m < 4; m++)
            CP_ASYNC16(bd + m * 16, wptr + (size_t)k0 * HID_ + m * 8);
        CP_COMMIT();
    };

    float acc[2][8][4];
#pragma unroll
    for (int mi = 0; mi < 2; mi++)
#pragma unroll
        for (int ni = 0; ni < 8; ni++)
#pragma unroll
            for (int j = 0; j < 4; j++) acc[mi][ni][j] = 0.f;

    issue(0, 0);

    for (int c = 0; c < NCHUNK; c++) {
        const int s = c & 1;
        if (c + 1 < NCHUNK) { issue(c + 1, s ^ 1); CP_WAIT1(); }
        else                { CP_WAIT0(); }
        __syncthreads();

        const __half* As = AsBase + s * GEMM_AS_STG;
        const __half* Bs = BsBase + s * GEMM_BS_STG;

#pragma unroll
        for (int kk = 0; kk < 4; kk++) {
            uint32_t af[2][4];
#pragma unroll
            for (int mi = 0; mi < 2; mi++)
                ldsm4(af[mi], smaddr(&As[(wm * 32 + mi * 16 + (lane & 15)) * LDAH
                                         + kk * 16 + ((lane >> 4) << 3)]));
            uint32_t bf[8][2];
#pragma unroll
            for (int nip = 0; nip < 4; nip++) {
                uint32_t t[4];
                ldsm4t(t, smaddr(&Bs[(kk * 16 + (lane & 7) + (((lane >> 3) & 1) << 3)) * LDBH
                                     + wn * 64 + nip * 16 + ((lane >> 4) << 3)]));
                bf[nip * 2][0]     = t[0]; bf[nip * 2][1]     = t[1];
                bf[nip * 2 + 1][0] = t[2]; bf[nip * 2 + 1][1] = t[3];
            }
#pragma unroll
            for (int mi = 0; mi < 2; mi++)
#pragma unroll
                for (int ni = 0; ni < 8; ni++)
                    mma_f16(acc[mi][ni], af[mi], bf[ni]);
        }
        __syncthreads();
    }

#pragma unroll
    for (int mi = 0; mi < 2; mi++) {
        const int row = brow + wm * 32 + mi * 16 + gq;
#pragma unroll
        for (int ni = 0; ni < 8; ni++) {
            const int col = bcol + wn * 64 + ni * 8 + lq * 2;
            const float b0 = bias[col], b1 = bias[col + 1];
            if (OUTH) {
                __half* Ch = (__half*)gb.C[z];
                *(uint32_t*)(Ch + (size_t)row * HID_ + col) =
                    h2u(__floats2half2_rn(acc[mi][ni][0] + b0, acc[mi][ni][1] + b1));
                *(uint32_t*)(Ch + (size_t)(row + 8) * HID_ + col) =
                    h2u(__floats2half2_rn(acc[mi][ni][2] + b0, acc[mi][ni][3] + b1));
            } else {
                float* Cf = (float*)gb.C[z];
                *(float2*)(Cf + (size_t)row * HID_ + col) =
                    make_float2(acc[mi][ni][0] + b0, acc[mi][ni][1] + b1);
                *(float2*)(Cf + (size_t)(row + 8) * HID_ + col) =
                    make_float2(acc[mi][ni][2] + b0, acc[mi][ni][3] + b1);
            }
        }
    }
}

// ================================================================
// Flash fp16-mma attention (unchanged from R15).
// ================================================================
#define KT_STR   4608
#define AT_VS    9216
#define AT_SRL   18432
#define ATTN_SMEM 51456
#define NKT 32

__global__ __launch_bounds__(128, 4)
void attn_mma_kernel(const float* __restrict__ relEmb)
{
    extern __shared__ char smc[];
    __half* Qs  = (__half*)(smc);               // alias (prologue only)
    __half* Rel = (__half*)(smc);               // alias (prologue only)
    __half* Srl = (__half*)(smc + AT_SRL);

    const int tid  = threadIdx.x;
    const int wid  = tid >> 5;
    const int lane = tid & 31;
    const int gq   = lane >> 2;
    const int lq   = lane & 3;

    const int bq = blockIdx.x * 64;
    const int h  = blockIdx.y;
    const int bb = blockIdx.z;

    // ---- prologue: Q tile scaled by (1/sqrt(d))*log2e -> exp2 domain ----
    {
        const int row = tid >> 1;
        const int cb  = (tid & 1) * 32;
        const __half* qp = g_Q + (size_t)(bb * S_ + bq + row) * HID_ + h * HD + cb;
        const __half2 sc = __floats2half2_rn(INV_SCALE * LOG2E, INV_SCALE * LOG2E);
#pragma unroll
        for (int j = 0; j < 4; j++) {
            uint4 v = *(const uint4*)(qp + j * 8);
            __half2* hv = (__half2*)&v;
            hv[0] = __hmul2(hv[0], sc); hv[1] = __hmul2(hv[1], sc);
            hv[2] = __hmul2(hv[2], sc); hv[3] = __hmul2(hv[3], sc);
            *(uint4*)&Qs[row * 72 + cb + j * 8] = v;
        }
    }
    __syncthreads();

    uint32_t qf[4][4];
#pragma unroll
    for (int kk = 0; kk < 4; kk++)
        ldsm4(qf[kk], smaddr(&Qs[(wid * 16 + (lane & 15)) * 72
                                 + kk * 16 + ((lane >> 4) << 3)]));

    const int r0 = wid * 16 + gq;
    const int r1 = r0 + 8;

    // ---- fused s_rel (exp2 domain) in 3 staged chunks ----
    for (int c = 0; c < 3; c++) {
        const int nrows  = (c < 2) ? 128 : 16;
        const int ntiles = (c < 2) ? 8 : 1;
        __syncthreads();
        if (tid < nrows) {
            const int rr = c * 128 + tid;
            if (rr < RTAB) {
                const float* rp = relEmb + (size_t)rr * HD;
#pragma unroll
                for (int j = 0; j < 8; j++) {
                    float4 a  = *(const float4*)(rp + j * 8);
                    float4 b2 = *(const float4*)(rp + j * 8 + 4);
                    uint4 u;
                    u.x = h2u(__floats2half2_rn(a.x, a.y));
                    u.y = h2u(__floats2half2_rn(a.z, a.w));
                    u.z = h2u(__floats2half2_rn(b2.x, b2.y));
                    u.w = h2u(__floats2half2_rn(b2.z, b2.w));
                    *(uint4*)&Rel[tid * 72 + j * 8] = u;
                }
            } else {
#pragma unroll
                for (int j = 0; j < 8; j++)
                    *(uint4*)&Rel[tid * 72 + j * 8] = make_uint4(0, 0, 0, 0);
            }
        }
        __syncthreads();

        for (int t = 0; t < ntiles; t++) {
            const int p  = c * 8 + t;
            const int n0 = p * 16;
            float c0[4] = {0.f, 0.f, 0.f, 0.f}, c1[4] = {0.f, 0.f, 0.f, 0.f};
            const uint32_t rb = smaddr(&Rel[(t * 16 + (lane & 7) + ((lane >> 4) << 3)) * 72]);
#pragma unroll
            for (int kk = 0; kk < 4; kk++) {
                uint32_t t4[4];
                ldsm4(t4, rb + (kk * 16 + (((lane >> 3) & 1) << 3)) * 2);
                uint32_t b0[2] = {t4[0], t4[1]}, b1v[2] = {t4[2], t4[3]};
                mma_f16(c0, qf[kk], b0);
                mma_f16(c1, qf[kk], b1v);
            }
            const int ca = n0 + lq * 2;
            if (ca <= 256) {
                *(uint32_t*)&Srl[r0 * 258 + ca] = h2u(__floats2half2_rn(c0[0], c0[1]));
                *(uint32_t*)&Srl[r1 * 258 + ca] = h2u(__floats2half2_rn(c0[2], c0[3]));
            }
            const int cbn = n0 + 8 + lq * 2;
            if (cbn <= 256) {
                *(uint32_t*)&Srl[r0 * 258 + cbn] = h2u(__floats2half2_rn(c1[0], c1[1]));
                *(uint32_t*)&Srl[r1 * 258 + cbn] = h2u(__floats2half2_rn(c1[2], c1[3]));
            }
        }
    }
    if (lq == 0) {
        const __half s = __float2half(-60000.f);
        Srl[r0 * 258 + 257] = s;
        Srl[r1 * 258 + 257] = s;
    }
    __syncthreads();   // Rel alias fully consumed before K/V issue

    // ---- K/V issue: 32-row tile, 4 threads/row, 2 units each ----
    const int kvrow = tid >> 2;
    const int kvu   = tid & 3;
    const __half* kbase = g_K + (size_t)(bb * S_ + kvrow) * HID_ + h * HD;
    const __half* vbase = g_V + (size_t)(bb * S_ + kvrow) * HID_ + h * HD;

    auto issueKV = [&](int kt) {
        const int s = kt & 1;
        const __half* kp = kbase + (size_t)(kt * 32) * HID_;
        const __half* vp = vbase + (size_t)(kt * 32) * HID_;
        const uint32_t kd = smaddr(smc + s * KT_STR)         + kvrow * 144;
        const uint32_t vd = smaddr(smc + AT_VS + s * KT_STR) + kvrow * 144;
#pragma unroll
        for (int j = 0; j < 2; j++) {
            const int u = kvu + j * 4;
            CP_ASYNC16(kd + u * 16, kp + u * 8);
            CP_ASYNC16(vd + u * 16, vp + u * 8);
        }
        CP_COMMIT();
    };

    issueKV(0);

    float oacc[8][4];
#pragma unroll
    for (int ni = 0; ni < 8; ni++)
#pragma unroll
        for (int j = 0; j < 4; j++) oacc[ni][j] = 0.f;
    float l0 = 0.f, l1 = 0.f;

    const size_t qg0 = (size_t)(bb * S_ + bq + r0);
    const size_t qg1 = qg0 + 8;
    const uint16_t* pP0 = g_pidx + qg0 * S_ + lq * 8;
    const uint16_t* pP1 = g_pidx + qg1 * S_ + lq * 8;
    const __half*   sR0 = &Srl[r0 * 258];
    const __half*   sR1 = &Srl[r1 * 258];

    for (int kt = 0; kt < NKT; kt++) {
        const int s = kt & 1;
        __half* Kt = (__half*)(smc + s * KT_STR);
        __half* Vs = (__half*)(smc + AT_VS + s * KT_STR);
        const int k0 = kt * 32;

        const uint4 u0 = *(const uint4*)(pP0 + k0);
        const uint4 u1 = *(const uint4*)(pP1 + k0);
        const uint32_t i0p[4] = {u0.x, u0.y, u0.z, u0.w};
        const uint32_t i1p[4] = {u1.x, u1.y, u1.z, u1.w};

        CP_WAIT0();
        __syncthreads();
        if (kt + 1 < NKT) issueKV(kt + 1);

        // ---- S = Q K^T  (warp: 16 x 32; exp2 domain) ----
        float sacc[4][4];
#pragma unroll
        for (int ni = 0; ni < 4; ni++)
#pragma unroll
            for (int j = 0; j < 4; j++) sacc[ni][j] = 0.f;

#pragma unroll
        for (int kk = 0; kk < 4; kk++) {
#pragma unroll
            for (int p = 0; p < 2; p++) {
                uint32_t t[4];
                ldsm4(t, smaddr(&Kt[(p * 16 + (lane & 7) + ((lane >> 4) << 3)) * 72
                                    + kk * 16 + (((lane >> 3) & 1) << 3)]));
                uint32_t b0[2] = {t[0], t[1]}, b1v[2] = {t[2], t[3]};
                mma_f16(sacc[p * 2],     qf[kk], b0);
                mma_f16(sacc[p * 2 + 1], qf[kk], b1v);
            }
        }

        // ---- bias gather + P = 2^s ----
        uint32_t pa[2][4];
#pragma unroll
        for (int j = 0; j < 2; j++) {
            float p0 = ex2(sacc[2 * j][0] + __half2float(sR0[i0p[2 * j] & 0xFFFF]));
            float p1 = ex2(sacc[2 * j][1] + __half2float(sR0[i0p[2 * j] >> 16]));
            float p2 = ex2(sacc[2 * j][2] + __half2float(sR1[i1p[2 * j] & 0xFFFF]));
            float p3 = ex2(sacc[2 * j][3] + __half2float(sR1[i1p[2 * j] >> 16]));
            float p4 = ex2(sacc[2 * j + 1][0] + __half2float(sR0[i0p[2 * j + 1] & 0xFFFF]));
            float p5 = ex2(sacc[2 * j + 1][1] + __half2float(sR0[i0p[2 * j + 1] >> 16]));
            float p6 = ex2(sacc[2 * j + 1][2] + __half2float(sR1[i1p[2 * j + 1] & 0xFFFF]));
            float p7 = ex2(sacc[2 * j + 1][3] + __half2float(sR1[i1p[2 * j + 1] >> 16]));
            pa[j][0] = h2u(__floats2half2_rn(p0, p1));
            pa[j][1] = h2u(__floats2half2_rn(p2, p3));
            pa[j][2] = h2u(__floats2half2_rn(p4, p5));
            pa[j][3] = h2u(__floats2half2_rn(p6, p7));
            l0 += p0 + p1 + p4 + p5;
            l1 += p2 + p3 + p6 + p7;
        }

        // ---- O += P V ----
#pragma unroll
        for (int j = 0; j < 2; j++) {
#pragma unroll
            for (int dp = 0; dp < 4; dp++) {
                uint32_t t[4];
                ldsm4t(t, smaddr(&Vs[(j * 16 + (lane & 7) + (((lane >> 3) & 1) << 3)) * 72
                                     + dp * 16 + ((lane >> 4) << 3)]));
                uint32_t b0[2] = {t[0], t[1]}, b1v[2] = {t[2], t[3]};
                mma_f16(oacc[dp * 2],     pa[j], b0);
                mma_f16(oacc[dp * 2 + 1], pa[j], b1v);
            }
        }
    }

    // ---- deferred row-sum reduction + output ----
#pragma unroll
    for (int o = 1; o <= 2; o <<= 1) {
        l0 += __shfl_xor_sync(0xffffffffu, l0, o);
        l1 += __shfl_xor_sync(0xffffffffu, l1, o);
    }
    const float i0 = 1.0f / l0;
    const float i1 = 1.0f / l1;
#pragma unroll
    for (int ni = 0; ni < 8; ni++) {
        const int col = h * HD + ni * 8 + lq * 2;
        *(uint32_t*)(g_X + qg0 * HID_ + col) =
            h2u(__floats2half2_rn(oacc[ni][0] * i0, oacc[ni][1] * i0));
        *(uint32_t*)(g_X + qg1 * HID_ + col) =
            h2u(__floats2half2_rn(oacc[ni][2] * i1, oacc[ni][3] * i1));
    }
}

// ================================================================
// launch
// ================================================================
extern "C" void kernel_launch(void* const* d_in, const int* in_sizes, int n_in,
                              void* d_out, int out_size)
{
    const float*   query   = (const float*)d_in[0];
    const float*   key     = (const float*)d_in[1];
    const float*   value   = (const float*)d_in[2];
    const uint8_t* mask    = (const uint8_t*)d_in[3];
    const int*     reldist = (const int*)d_in[4];
    const float*   Wq = (const float*)d_in[5];
    const float*   bq = (const float*)d_in[6];
    const float*   Wk = (const float*)d_in[7];
    const float*   bk = (const float*)d_in[8];
    const float*   Wv = (const float*)d_in[9];
    const float*   bv = (const float*)d_in[10];
    const float*   Wo = (const float*)d_in[11];
    const float*   bo = (const float*)d_in[12];
    const float*   rel_emb = (const float*)d_in[13];
    float* out = (float*)d_out;

    __half *Qp, *Kp, *Vp, *Xp, *A16p, *W16p;
    cudaGetSymbolAddress((void**)&Qp,   g_Q);
    cudaGetSymbolAddress((void**)&Kp,   g_K);
    cudaGetSymbolAddress((void**)&Vp,   g_V);
    cudaGetSymbolAddress((void**)&Xp,   g_X);
    cudaGetSymbolAddress((void**)&A16p, g_A16);
    cudaGetSymbolAddress((void**)&W16p, g_W16);

    const int NIN = B_ * S_ * HID_;
    const int NW  = HID_ * HID_;
    __half* a16[3] = { A16p, A16p + NIN, A16p + 2 * NIN };
    __half* w16[4] = { W16p, W16p + NW, W16p + 2 * NW, W16p + 3 * NW };

    cudaFuncSetAttribute(attn_mma_kernel, cudaFuncAttributeMaxDynamicSharedMemorySize, ATTN_SMEM);
    cudaFuncSetAttribute(gemm_mma_kernel<1>, cudaFuncAttributeMaxDynamicSharedMemorySize, GEMM_SMEM);
    cudaFuncSetAttribute(gemm_mma_kernel<0>, cudaFuncAttributeMaxDynamicSharedMemorySize, GEMM_SMEM);

    pack_kernel<<<(B_ * S_ * S_ / 8) / 256, 256>>>(reldist, mask);
    {
        CvtArgs ca;
        ca.src[0] = query; ca.src[1] = key; ca.src[2] = value;
        ca.src[3] = Wq; ca.src[4] = Wk; ca.src[5] = Wv; ca.src[6] = Wo;
        ca.dst[0] = a16[0]; ca.dst[1] = a16[1]; ca.dst[2] = a16[2];
        ca.dst[3] = w16[0]; ca.dst[4] = w16[1]; ca.dst[5] = w16[2]; ca.dst[6] = w16[3];
        ca.n[0] = ca.n[1] = ca.n[2] = NIN;
        ca.n[3] = ca.n[4] = ca.n[5] = ca.n[6] = NW;
        cvt_kernel<<<dim3(NIN / (256 * 8), 7), 256>>>(ca);
    }

    {
        GemmBatch gb;
        gb.A[0] = a16[0]; gb.A[1] = a16[1]; gb.A[2] = a16[2];
        gb.W[0] = w16[0]; gb.W[1] = w16[1]; gb.W[2] = w16[2];
        gb.b[0] = bq; gb.b[1] = bk; gb.b[2] = bv;
        gb.C[0] = Qp; gb.C[1] = Kp; gb.C[2] = Vp;
        gemm_mma_kernel<1><<<dim3(HID_ / BN, (B_ * S_) / BM, 3), 256, GEMM_SMEM>>>(gb);
    }

    attn_mma_kernel<<<dim3(S_ / 64, NH, B_), 128, ATTN_SMEM>>>(rel_emb);

    {
        GemmBatch gb;
        gb.A[0] = Xp;     gb.A[1] = Xp;     gb.A[2] = Xp;
        gb.W[0] = w16[3]; gb.W[1] = w16[3]; gb.W[2] = w16[3];
        gb.b[0] = bo;     gb.b[1] = bo;     gb.b[2] = bo;
        gb.C[0] = out;    gb.C[1] = out;    gb.C[2] = out;
        gemm_mma_kernel<0><<<dim3(HID_ / BN, (B_ * S_) / BM, 1), 256, GEMM_SMEM>>>(gb);
    }
}

// round 17
// speedup vs baseline: 1.0600x; 1.0600x over previous
#include <cuda_runtime.h>
#include <cuda_fp16.h>
#include <cstdint>
#include <math.h>

#define B_   2
#define S_   1024
#define HID_ 1024
#define NH   16
#define HD   64
#define RTAB 257
#define MAXREL 128
#define INV_SCALE 0.125f   // 1/sqrt(64)
#define LOG2E 1.44269504089f

// ---------------- scratch (no allocations allowed) ----------------
__device__ __half   g_Q[B_ * S_ * HID_];
__device__ __half   g_K[B_ * S_ * HID_];
__device__ __half   g_V[B_ * S_ * HID_];
__device__ __half   g_X[B_ * S_ * HID_];
__device__ uint16_t g_pidx[B_ * S_ * S_];        // FRAGMENT-ORDER permuted indices
__device__ __half   g_A16[3][B_ * S_ * HID_];    // fp16 inputs (q,k,v)
__device__ __half   g_W16[4][HID_ * HID_];       // fp16 weights (Wq,Wk,Wv,Wo)

// ================================================================
// helpers
// ================================================================
__device__ __forceinline__ uint32_t smaddr(const void* p) {
    return (uint32_t)__cvta_generic_to_shared(p);
}
__device__ __forceinline__ uint32_t h2u(__half2 h) { return *(uint32_t*)&h; }
__device__ __forceinline__ float ex2(float x) {
    float y;
    asm("ex2.approx.f32 %0, %1;" : "=f"(y) : "f"(x));
    return y;
}

__device__ __forceinline__ void ldsm4(uint32_t* r, uint32_t a) {
    asm volatile("ldmatrix.sync.aligned.m8n8.x4.shared.b16 {%0,%1,%2,%3}, [%4];"
        : "=r"(r[0]), "=r"(r[1]), "=r"(r[2]), "=r"(r[3]) : "r"(a));
}
__device__ __forceinline__ void ldsm4t(uint32_t* r, uint32_t a) {
    asm volatile("ldmatrix.sync.aligned.m8n8.x4.trans.shared.b16 {%0,%1,%2,%3}, [%4];"
        : "=r"(r[0]), "=r"(r[1]), "=r"(r[2]), "=r"(r[3]) : "r"(a));
}
__device__ __forceinline__ void mma_f16(float* d, const uint32_t* a, const uint32_t* b) {
    asm volatile("mma.sync.aligned.m16n8k16.row.col.f32.f16.f16.f32 "
        "{%0,%1,%2,%3}, {%4,%5,%6,%7}, {%8,%9}, {%0,%1,%2,%3};"
        : "+f"(d[0]), "+f"(d[1]), "+f"(d[2]), "+f"(d[3])
        : "r"(a[0]), "r"(a[1]), "r"(a[2]), "r"(a[3]), "r"(b[0]), "r"(b[1]));
}
#define CP_ASYNC16(dst, src) \
    asm volatile("cp.async.cg.shared.global [%0], [%1], 16;" :: "r"(dst), "l"(src))
#define CP_COMMIT()  asm volatile("cp.async.commit_group;" ::: "memory")
#define CP_WAIT0()   asm volatile("cp.async.wait_group 0;" ::: "memory")
#define CP_WAIT1()   asm volatile("cp.async.wait_group 1;" ::: "memory")

// ================================================================
// pack dist+mask -> uint16 index, PERMUTED to mma fragment order
// ================================================================
__global__ __launch_bounds__(256)
void pack_kernel(const int* __restrict__ dist, const uint8_t* __restrict__ mask)
{
    const size_t idx  = (size_t)blockIdx.x * 256 + threadIdx.x;
    const size_t base = idx * 8;
    const int    k8   = (int)(base & (S_ - 1));
    const int    j    = (k8 >> 3) & 3;
    const size_t blkb = base - (size_t)(k8 & 31);

    int4   d0 = *(const int4*)(dist + base);
    int4   d1 = *(const int4*)(dist + base + 4);
    uchar4 m0 = *(const uchar4*)(mask + base);
    uchar4 m1 = *(const uchar4*)(mask + base + 4);

    uint16_t o[8];
    o[0] = m0.x ? 257 : (uint16_t)(d0.x + MAXREL);
    o[1] = m0.y ? 257 : (uint16_t)(d0.y + MAXREL);
    o[2] = m0.z ? 257 : (uint16_t)(d0.z + MAXREL);
    o[3] = m0.w ? 257 : (uint16_t)(d0.w + MAXREL);
    o[4] = m1.x ? 257 : (uint16_t)(d1.x + MAXREL);
    o[5] = m1.y ? 257 : (uint16_t)(d1.y + MAXREL);
    o[6] = m1.z ? 257 : (uint16_t)(d1.z + MAXREL);
    o[7] = m1.w ? 257 : (uint16_t)(d1.w + MAXREL);

#pragma unroll
    for (int lq = 0; lq < 4; lq++) {
        uint32_t pair = (uint32_t)o[2 * lq] | ((uint32_t)o[2 * lq + 1] << 16);
        *(uint32_t*)(g_pidx + blkb + lq * 8 + j * 2) = pair;
    }
}

// ================================================================
// fp32 -> fp16 convert, 7 segments
// ================================================================
struct CvtArgs {
    const float* src[7];
    __half*      dst[7];
    int          n[7];
};

__global__ __launch_bounds__(256)
void cvt_kernel(CvtArgs ca)
{
    const int seg = blockIdx.y;
    const int i   = blockIdx.x * 256 + threadIdx.x;
    if (i * 8 >= ca.n[seg]) return;
    const float4* sp = (const float4*)ca.src[seg] + i * 2;
    float4 a = sp[0], b2 = sp[1];
    uint4 u;
    u.x = h2u(__floats2half2_rn(a.x, a.y));
    u.y = h2u(__floats2half2_rn(a.z, a.w));
    u.z = h2u(__floats2half2_rn(b2.x, b2.y));
    u.w = h2u(__floats2half2_rn(b2.z, b2.w));
    ((uint4*)ca.dst[seg])[i] = u;
}

// ================================================================
// fp16 HMMA GEMM, cp.async double-buffered, BK=32 (R15-proven; 37.9KB static).
// ================================================================
#define BM 128
#define BN 128
#define BKC 32
#define NCHUNK (HID_ / BKC)
#define LDAH 40
#define LDBH 136

struct GemmBatch {
    const __half* A[3];
    const __half* W[3];
    const float*  b[3];
    void*         C[3];
};

template<int OUTH>
__global__ __launch_bounds__(256)
void gemm_mma_kernel(GemmBatch gb)
{
    __shared__ __half As[2][BM * LDAH];
    __shared__ __half Bs[2][BKC * LDBH];

    const int z = blockIdx.z;
    const __half* A    = gb.A[z];
    const __half* W    = gb.W[z];
    const float*  bias = gb.b[z];

    const int tid  = threadIdx.x;
    const int wid  = tid >> 5;
    const int lane = tid & 31;
    const int wm   = wid & 3;
    const int wn   = wid >> 2;
    const int gq   = lane >> 2;
    const int lq   = lane & 3;

    const int brow = blockIdx.y * BM;
    const int bcol = blockIdx.x * BN;

    const int arow = tid >> 1;
    const int au   = tid & 1;
    const int bro  = tid >> 3;
    const int bu   = tid & 7;

    const __half* aptr = A + (size_t)(brow + arow) * HID_;
    const __half* wptr = W + (size_t)bro * HID_ + bcol;

    auto issue = [&](int c, int s) {
        const int k0 = c * BKC;
#pragma unroll
        for (int j = 0; j < 2; j++) {
            const int u = au + j * 2;
            CP_ASYNC16(smaddr(&As[s][arow * LDAH + u * 8]), aptr + k0 + u * 8);
        }
#pragma unroll
        for (int j = 0; j < 2; j++) {
            const int u = bu + j * 8;
            CP_ASYNC16(smaddr(&Bs[s][bro * LDBH + u * 8]),
                       wptr + (size_t)k0 * HID_ + u * 8);
        }
        CP_COMMIT();
    };

    float acc[2][8][4];
#pragma unroll
    for (int mi = 0; mi < 2; mi++)
#pragma unroll
        for (int ni = 0; ni < 8; ni++)
#pragma unroll
            for (int j = 0; j < 4; j++) acc[mi][ni][j] = 0.f;

    issue(0, 0);

    for (int c = 0; c < NCHUNK; c++) {
        const int s = c & 1;
        if (c + 1 < NCHUNK) { issue(c + 1, s ^ 1); CP_WAIT1(); }
        else                { CP_WAIT0(); }
        __syncthreads();

#pragma unroll
        for (int kk = 0; kk < 2; kk++) {
            uint32_t af[2][4];
#pragma unroll
            for (int mi = 0; mi < 2; mi++)
                ldsm4(af[mi], smaddr(&As[s][(wm * 32 + mi * 16 + (lane & 15)) * LDAH
                                           + kk * 16 + ((lane >> 4) << 3)]));
            uint32_t bf[8][2];
#pragma unroll
            for (int nip = 0; nip < 4; nip++) {
                uint32_t t[4];
                ldsm4t(t, smaddr(&Bs[s][(kk * 16 + (lane & 7) + (((lane >> 3) & 1) << 3)) * LDBH
                                        + wn * 64 + nip * 16 + ((lane >> 4) << 3)]));
                bf[nip * 2][0]     = t[0]; bf[nip * 2][1]     = t[1];
                bf[nip * 2 + 1][0] = t[2]; bf[nip * 2 + 1][1] = t[3];
            }
#pragma unroll
            for (int mi = 0; mi < 2; mi++)
#pragma unroll
                for (int ni = 0; ni < 8; ni++)
                    mma_f16(acc[mi][ni], af[mi], bf[ni]);
        }
        __syncthreads();
    }

#pragma unroll
    for (int mi = 0; mi < 2; mi++) {
        const int row = brow + wm * 32 + mi * 16 + gq;
#pragma unroll
        for (int ni = 0; ni < 8; ni++) {
            const int col = bcol + wn * 64 + ni * 8 + lq * 2;
            const float b0 = bias[col], b1 = bias[col + 1];
            if (OUTH) {
                __half* Ch = (__half*)gb.C[z];
                *(uint32_t*)(Ch + (size_t)row * HID_ + col) =
                    h2u(__floats2half2_rn(acc[mi][ni][0] + b0, acc[mi][ni][1] + b1));
                *(uint32_t*)(Ch + (size_t)(row + 8) * HID_ + col) =
                    h2u(__floats2half2_rn(acc[mi][ni][2] + b0, acc[mi][ni][3] + b1));
            } else {
                float* Cf = (float*)gb.C[z];
                *(float2*)(Cf + (size_t)row * HID_ + col) =
                    make_float2(acc[mi][ni][0] + b0, acc[mi][ni][1] + b1);
                *(float2*)(Cf + (size_t)(row + 8) * HID_ + col) =
                    make_float2(acc[mi][ni][2] + b0, acc[mi][ni][3] + b1);
            }
        }
    }
}

// ================================================================
// Flash fp16-mma attention; Srl gather LDS hoisted before pipeline wait
// so its latency hides under the QK^T mma block.
// ================================================================
#define KT_STR   4608
#define AT_VS    9216
#define AT_SRL   18432
#define ATTN_SMEM 51456
#define NKT 32

__global__ __launch_bounds__(128, 4)
void attn_mma_kernel(const float* __restrict__ relEmb)
{
    extern __shared__ char smc[];
    __half* Qs  = (__half*)(smc);               // alias (prologue only)
    __half* Rel = (__half*)(smc);               // alias (prologue only)
    __half* Srl = (__half*)(smc + AT_SRL);

    const int tid  = threadIdx.x;
    const int wid  = tid >> 5;
    const int lane = tid & 31;
    const int gq   = lane >> 2;
    const int lq   = lane & 3;

    const int bq = blockIdx.x * 64;
    const int h  = blockIdx.y;
    const int bb = blockIdx.z;

    // ---- prologue: Q tile scaled by (1/sqrt(d))*log2e -> exp2 domain ----
    {
        const int row = tid >> 1;
        const int cb  = (tid & 1) * 32;
        const __half* qp = g_Q + (size_t)(bb * S_ + bq + row) * HID_ + h * HD + cb;
        const __half2 sc = __floats2half2_rn(INV_SCALE * LOG2E, INV_SCALE * LOG2E);
#pragma unroll
        for (int j = 0; j < 4; j++) {
            uint4 v = *(const uint4*)(qp + j * 8);
            __half2* hv = (__half2*)&v;
            hv[0] = __hmul2(hv[0], sc); hv[1] = __hmul2(hv[1], sc);
            hv[2] = __hmul2(hv[2], sc); hv[3] = __hmul2(hv[3], sc);
            *(uint4*)&Qs[row * 72 + cb + j * 8] = v;
        }
    }
    __syncthreads();

    uint32_t qf[4][4];
#pragma unroll
    for (int kk = 0; kk < 4; kk++)
        ldsm4(qf[kk], smaddr(&Qs[(wid * 16 + (lane & 15)) * 72
                                 + kk * 16 + ((lane >> 4) << 3)]));

    const int r0 = wid * 16 + gq;
    const int r1 = r0 + 8;

    // ---- fused s_rel (exp2 domain) in 3 staged chunks ----
    for (int c = 0; c < 3; c++) {
        const int nrows  = (c < 2) ? 128 : 16;
        const int ntiles = (c < 2) ? 8 : 1;
        __syncthreads();
        if (tid < nrows) {
            const int rr = c * 128 + tid;
            if (rr < RTAB) {
                const float* rp = relEmb + (size_t)rr * HD;
#pragma unroll
                for (int j = 0; j < 8; j++) {
                    float4 a  = *(const float4*)(rp + j * 8);
                    float4 b2 = *(const float4*)(rp + j * 8 + 4);
                    uint4 u;
                    u.x = h2u(__floats2half2_rn(a.x, a.y));
                    u.y = h2u(__floats2half2_rn(a.z, a.w));
                    u.z = h2u(__floats2half2_rn(b2.x, b2.y));
                    u.w = h2u(__floats2half2_rn(b2.z, b2.w));
                    *(uint4*)&Rel[tid * 72 + j * 8] = u;
                }
            } else {
#pragma unroll
                for (int j = 0; j < 8; j++)
                    *(uint4*)&Rel[tid * 72 + j * 8] = make_uint4(0, 0, 0, 0);
            }
        }
        __syncthreads();

        for (int t = 0; t < ntiles; t++) {
            const int p  = c * 8 + t;
            const int n0 = p * 16;
            float c0[4] = {0.f, 0.f, 0.f, 0.f}, c1[4] = {0.f, 0.f, 0.f, 0.f};
            const uint32_t rb = smaddr(&Rel[(t * 16 + (lane & 7) + ((lane >> 4) << 3)) * 72]);
#pragma unroll
            for (int kk = 0; kk < 4; kk++) {
                uint32_t t4[4];
                ldsm4(t4, rb + (kk * 16 + (((lane >> 3) & 1) << 3)) * 2);
                uint32_t b0[2] = {t4[0], t4[1]}, b1v[2] = {t4[2], t4[3]};
                mma_f16(c0, qf[kk], b0);
                mma_f16(c1, qf[kk], b1v);
            }
            const int ca = n0 + lq * 2;
            if (ca <= 256) {
                *(uint32_t*)&Srl[r0 * 258 + ca] = h2u(__floats2half2_rn(c0[0], c0[1]));
                *(uint32_t*)&Srl[r1 * 258 + ca] = h2u(__floats2half2_rn(c0[2], c0[3]));
            }
            const int cbn = n0 + 8 + lq * 2;
            if (cbn <= 256) {
                *(uint32_t*)&Srl[r0 * 258 + cbn] = h2u(__floats2half2_rn(c1[0], c1[1]));
                *(uint32_t*)&Srl[r1 * 258 + cbn] = h2u(__floats2half2_rn(c1[2], c1[3]));
            }
        }
    }
    if (lq == 0) {
        const __half s = __float2half(-60000.f);
        Srl[r0 * 258 + 257] = s;
        Srl[r1 * 258 + 257] = s;
    }
    __syncthreads();   // Rel alias fully consumed before K/V issue

    // ---- K/V issue: 32-row tile, 4 threads/row, 2 units each ----
    const int kvrow = tid >> 2;
    const int kvu   = tid & 3;
    const __half* kbase = g_K + (size_t)(bb * S_ + kvrow) * HID_ + h * HD;
    const __half* vbase = g_V + (size_t)(bb * S_ + kvrow) * HID_ + h * HD;

    auto issueKV = [&](int kt) {
        const int s = kt & 1;
        const __half* kp = kbase + (size_t)(kt * 32) * HID_;
        const __half* vp = vbase + (size_t)(kt * 32) * HID_;
        const uint32_t kd = smaddr(smc + s * KT_STR)         + kvrow * 144;
        const uint32_t vd = smaddr(smc + AT_VS + s * KT_STR) + kvrow * 144;
#pragma unroll
        for (int j = 0; j < 2; j++) {
            const int u = kvu + j * 4;
            CP_ASYNC16(kd + u * 16, kp + u * 8);
            CP_ASYNC16(vd + u * 16, vp + u * 8);
        }
        CP_COMMIT();
    };

    issueKV(0);

    float oacc[8][4];
#pragma unroll
    for (int ni = 0; ni < 8; ni++)
#pragma unroll
        for (int j = 0; j < 4; j++) oacc[ni][j] = 0.f;
    float l0 = 0.f, l1 = 0.f;

    const size_t qg0 = (size_t)(bb * S_ + bq + r0);
    const size_t qg1 = qg0 + 8;
    const uint16_t* pP0 = g_pidx + qg0 * S_ + lq * 8;
    const uint16_t* pP1 = g_pidx + qg1 * S_ + lq * 8;
    const __half*   sR0 = &Srl[r0 * 258];
    const __half*   sR1 = &Srl[r1 * 258];

    for (int kt = 0; kt < NKT; kt++) {
        const int s = kt & 1;
        __half* Kt = (__half*)(smc + s * KT_STR);
        __half* Vs = (__half*)(smc + AT_VS + s * KT_STR);
        const int k0 = kt * 32;

        // indices (one LDG.128 per row) + EARLY Srl gathers: issue the 16
        // random LDS now so their latency hides under the QK^T mma below.
        const uint4 u0 = *(const uint4*)(pP0 + k0);
        const uint4 u1 = *(const uint4*)(pP1 + k0);
        const uint32_t i0p[4] = {u0.x, u0.y, u0.z, u0.w};
        const uint32_t i1p[4] = {u1.x, u1.y, u1.z, u1.w};
        float bv0[8], bv1[8];
#pragma unroll
        for (int j = 0; j < 4; j++) {
            bv0[2 * j]     = __half2float(sR0[i0p[j] & 0xFFFF]);
            bv0[2 * j + 1] = __half2float(sR0[i0p[j] >> 16]);
            bv1[2 * j]     = __half2float(sR1[i1p[j] & 0xFFFF]);
            bv1[2 * j + 1] = __half2float(sR1[i1p[j] >> 16]);
        }

        CP_WAIT0();
        __syncthreads();
        if (kt + 1 < NKT) issueKV(kt + 1);

        // ---- S = Q K^T  (warp: 16 x 32; exp2 domain) ----
        float sacc[4][4];
#pragma unroll
        for (int ni = 0; ni < 4; ni++)
#pragma unroll
            for (int j = 0; j < 4; j++) sacc[ni][j] = 0.f;

#pragma unroll
        for (int kk = 0; kk < 4; kk++) {
#pragma unroll
            for (int p = 0; p < 2; p++) {
                uint32_t t[4];
                ldsm4(t, smaddr(&Kt[(p * 16 + (lane & 7) + ((lane >> 4) << 3)) * 72
                                    + kk * 16 + (((lane >> 3) & 1) << 3)]));
                uint32_t b0[2] = {t[0], t[1]}, b1v[2] = {t[2], t[3]};
                mma_f16(sacc[p * 2],     qf[kk], b0);
                mma_f16(sacc[p * 2 + 1], qf[kk], b1v);
            }
        }

        // ---- P = 2^(s + bias) using pre-gathered bias values ----
        uint32_t pa[2][4];
#pragma unroll
        for (int j = 0; j < 2; j++) {
            float p0 = ex2(sacc[2 * j][0] + bv0[4 * j]);
            float p1 = ex2(sacc[2 * j][1] + bv0[4 * j + 1]);
            float p2 = ex2(sacc[2 * j][2] + bv1[4 * j]);
            float p3 = ex2(sacc[2 * j][3] + bv1[4 * j + 1]);
            float p4 = ex2(sacc[2 * j + 1][0] + bv0[4 * j + 2]);
            float p5 = ex2(sacc[2 * j + 1][1] + bv0[4 * j + 3]);
            float p6 = ex2(sacc[2 * j + 1][2] + bv1[4 * j + 2]);
            float p7 = ex2(sacc[2 * j + 1][3] + bv1[4 * j + 3]);
            pa[j][0] = h2u(__floats2half2_rn(p0, p1));
            pa[j][1] = h2u(__floats2half2_rn(p2, p3));
            pa[j][2] = h2u(__floats2half2_rn(p4, p5));
            pa[j][3] = h2u(__floats2half2_rn(p6, p7));
            l0 += p0 + p1 + p4 + p5;
            l1 += p2 + p3 + p6 + p7;
        }

        // ---- O += P V ----
#pragma unroll
        for (int j = 0; j < 2; j++) {
#pragma unroll
            for (int dp = 0; dp < 4; dp++) {
                uint32_t t[4];
                ldsm4t(t, smaddr(&Vs[(j * 16 + (lane & 7) + (((lane >> 3) & 1) << 3)) * 72
                                     + dp * 16 + ((lane >> 4) << 3)]));
                uint32_t b0[2] = {t[0], t[1]}, b1v[2] = {t[2], t[3]};
                mma_f16(oacc[dp * 2],     pa[j], b0);
                mma_f16(oacc[dp * 2 + 1], pa[j], b1v);
            }
        }
    }

    // ---- deferred row-sum reduction + output ----
#pragma unroll
    for (int o = 1; o <= 2; o <<= 1) {
        l0 += __shfl_xor_sync(0xffffffffu, l0, o);
        l1 += __shfl_xor_sync(0xffffffffu, l1, o);
    }
    const float i0 = 1.0f / l0;
    const float i1 = 1.0f / l1;
#pragma unroll
    for (int ni = 0; ni < 8; ni++) {
        const int col = h * HD + ni * 8 + lq * 2;
        *(uint32_t*)(g_X + qg0 * HID_ + col) =
            h2u(__floats2half2_rn(oacc[ni][0] * i0, oacc[ni][1] * i0));
        *(uint32_t*)(g_X + qg1 * HID_ + col) =
            h2u(__floats2half2_rn(oacc[ni][2] * i1, oacc[ni][3] * i1));
    }
}

// ================================================================
// launch
// ================================================================
extern "C" void kernel_launch(void* const* d_in, const int* in_sizes, int n_in,
                              void* d_out, int out_size)
{
    const float*   query   = (const float*)d_in[0];
    const float*   key     = (const float*)d_in[1];
    const float*   value   = (const float*)d_in[2];
    const uint8_t* mask    = (const uint8_t*)d_in[3];
    const int*     reldist = (const int*)d_in[4];
    const float*   Wq = (const float*)d_in[5];
    const float*   bq = (const float*)d_in[6];
    const float*   Wk = (const float*)d_in[7];
    const float*   bk = (const float*)d_in[8];
    const float*   Wv = (const float*)d_in[9];
    const float*   bv = (const float*)d_in[10];
    const float*   Wo = (const float*)d_in[11];
    const float*   bo = (const float*)d_in[12];
    const float*   rel_emb = (const float*)d_in[13];
    float* out = (float*)d_out;

    __half *Qp, *Kp, *Vp, *Xp, *A16p, *W16p;
    cudaGetSymbolAddress((void**)&Qp,   g_Q);
    cudaGetSymbolAddress((void**)&Kp,   g_K);
    cudaGetSymbolAddress((void**)&Vp,   g_V);
    cudaGetSymbolAddress((void**)&Xp,   g_X);
    cudaGetSymbolAddress((void**)&A16p, g_A16);
    cudaGetSymbolAddress((void**)&W16p, g_W16);

    const int NIN = B_ * S_ * HID_;
    const int NW  = HID_ * HID_;
    __half* a16[3] = { A16p, A16p + NIN, A16p + 2 * NIN };
    __half* w16[4] = { W16p, W16p + NW, W16p + 2 * NW, W16p + 3 * NW };

    cudaFuncSetAttribute(attn_mma_kernel, cudaFuncAttributeMaxDynamicSharedMemorySize, ATTN_SMEM);

    pack_kernel<<<(B_ * S_ * S_ / 8) / 256, 256>>>(reldist, mask);
    {
        CvtArgs ca;
        ca.src[0] = query; ca.src[1] = key; ca.src[2] = value;
        ca.src[3] = Wq; ca.src[4] = Wk; ca.src[5] = Wv; ca.src[6] = Wo;
        ca.dst[0] = a16[0]; ca.dst[1] = a16[1]; ca.dst[2] = a16[2];
        ca.dst[3] = w16[0]; ca.dst[4] = w16[1]; ca.dst[5] = w16[2]; ca.dst[6] = w16[3];
        ca.n[0] = ca.n[1] = ca.n[2] = NIN;
        ca.n[3] = ca.n[4] = ca.n[5] = ca.n[6] = NW;
        cvt_kernel<<<dim3(NIN / (256 * 8), 7), 256>>>(ca);
    }

    {
        GemmBatch gb;
        gb.A[0] = a16[0]; gb.A[1] = a16[1]; gb.A[2] = a16[2];
        gb.W[0] = w16[0]; gb.W[1] = w16[1]; gb.W[2] = w16[2];
        gb.b[0] = bq; gb.b[1] = bk; gb.b[2] = bv;
        gb.C[0] = Qp; gb.C[1] = Kp; gb.C[2] = Vp;
        gemm_mma_kernel<1><<<dim3(HID_ / BN, (B_ * S_) / BM, 3), 256>>>(gb);
    }

    attn_mma_kernel<<<dim3(S_ / 64, NH, B_), 128, ATTN_SMEM>>>(rel_emb);

    {
        GemmBatch gb;
        gb.A[0] = Xp;     gb.A[1] = Xp;     gb.A[2] = Xp;
        gb.W[0] = w16[3]; gb.W[1] = w16[3]; gb.W[2] = w16[3];
        gb.b[0] = bo;     gb.b[1] = bo;     gb.b[2] = bo;
        gb.C[0] = out;    gb.C[1] = out;    gb.C[2] = out;
        gemm_mma_kernel<0><<<dim3(HID_ / BN, (B_ * S_) / BM, 1), 256>>>(gb);
    }
}